// round 6
// baseline (speedup 1.0000x reference)
#include <cuda_runtime.h>
#include <math.h>

#define D      128
#define RREL   500
#define NNODES 200000

// ---------------- device scratch ----------------
__device__ float2 g_acc[NNODES];      // .x = sum(selected·w1), .y = msg count
__device__ float  g_w1[D];            // (W_fin @ W_score)[0:D]
__device__ float  g_w2[D];            // (W_fin @ W_score)[D:2D]
__device__ float  g_ceff;             // b_fin·W_score + b_score
__device__ float  g_bdot[4];          // b_x · w1
__device__ float  g_P[4][RREL][D];    // P_x = rel_emb @ W_x
__device__ float  g_udot[RREL * 4];   // P_x[r] · w1  (== rel[r]·(W_x@w1))
__device__ float  g_reldot[RREL];     // rel[r] · w2

__device__ __forceinline__ float warp_sum(float v) {
#pragma unroll
    for (int o = 16; o > 0; o >>= 1) v += __shfl_down_sync(0xffffffffu, v, o);
    return v;
}

// ---------------- K_A: P_x GEMM + w_eff + ceff + zero g_acc ----------------
// blocks [0,128): GEMM tiles (x = b>>5, rtile = b&31, 16 rows each)
// blocks [128,161): w_eff warps + ceff
// all blocks: strided zero of g_acc
#define GA_BLOCKS 161
#define GA_NT     (GA_BLOCKS * 256)
__global__ void __launch_bounds__(256)
k_A(const float* __restrict__ rel_emb,
    const float* __restrict__ W_hh, const float* __restrict__ W_ht,
    const float* __restrict__ W_th, const float* __restrict__ W_tt,
    const float* __restrict__ W_fin, const float* __restrict__ b_fin,
    const float* __restrict__ W_score, const float* __restrict__ b_score) {
    const int tid = threadIdx.x;
    const int b   = blockIdx.x;
    const int gt  = b * 256 + tid;

    // zero g_acc (everyone)
    for (int i = gt; i < NNODES; i += GA_NT) g_acc[i] = make_float2(0.f, 0.f);

    if (b < 128) {
        // ---- GEMM tile: P_x[r0..r0+15][0..127] = rel[rows] @ W_x ----
        const float* Ws[4] = {W_hh, W_ht, W_th, W_tt};
        const int x  = b >> 5;
        const int rt = b & 31;
        const int r0 = rt * 16;
        const float* W = Ws[x];

        __shared__ float s_rel[16][D];     // 8KB
        __shared__ float s_part[16][D];    // 8KB
        for (int i = tid; i < 16 * D; i += 256) {
            int rr = r0 + (i >> 7);
            s_rel[i >> 7][i & 127] = (rr < RREL) ? rel_emb[rr * D + (i & 127)] : 0.f;
        }
        __syncthreads();

        const int d  = tid & 127;
        const int kh = tid >> 7;           // k-half: 0 or 1
        float acc[16];
#pragma unroll
        for (int i = 0; i < 16; i++) acc[i] = 0.f;
        const int k0 = kh * 64;
#pragma unroll 4
        for (int k = 0; k < 64; k++) {
            int kk = k0 + k;
            float w = W[kk * D + d];
#pragma unroll
            for (int i = 0; i < 16; i++) acc[i] += s_rel[i][kk] * w;
        }
        if (kh == 1) {
#pragma unroll
            for (int i = 0; i < 16; i++) s_part[i][d] = acc[i];
        }
        __syncthreads();
        if (kh == 0) {
#pragma unroll
            for (int i = 0; i < 16; i++) {
                int rr = r0 + i;
                if (rr < RREL) g_P[x][rr][d] = acc[i] + s_part[i][d];
            }
        }
    } else {
        // ---- w_eff (warp per row) + ceff ----
        const int lane = tid & 31;
        const int gw   = (b - 128) * 8 + (tid >> 5);   // 0..263
        if (gw < 256) {
            float v = 0.f;
#pragma unroll
            for (int i = 0; i < 4; i++) {
                int dd = lane + 32 * i;
                v += W_fin[gw * D + dd] * W_score[dd];
            }
            v = warp_sum(v);
            if (lane == 0) { if (gw < D) g_w1[gw] = v; else g_w2[gw - D] = v; }
        } else if (gw == 256) {
            float v = 0.f;
#pragma unroll
            for (int i = 0; i < 4; i++) {
                int dd = lane + 32 * i;
                v += b_fin[dd] * W_score[dd];
            }
            v = warp_sum(v);
            if (lane == 0) g_ceff = v + b_score[0];
        }
    }
}

// ---------------- K_B: udot / reldot / bdot ----------------
// warp per relation (gw < 500); warps 500..503: bdot
__global__ void __launch_bounds__(256)
k_B(const float* __restrict__ rel_emb,
    const float* __restrict__ b_hh, const float* __restrict__ b_ht,
    const float* __restrict__ b_th, const float* __restrict__ b_tt) {
    const int lane = threadIdx.x & 31;
    const int gw   = blockIdx.x * 8 + (threadIdx.x >> 5);
    if (gw < RREL) {
        const int r = gw;
        float w1v[4], w2v[4];
#pragma unroll
        for (int i = 0; i < 4; i++) {
            w1v[i] = g_w1[lane + 32 * i];
            w2v[i] = g_w2[lane + 32 * i];
        }
#pragma unroll
        for (int x = 0; x < 4; x++) {
            const float* Pr = g_P[x][r];
            float v = 0.f;
#pragma unroll
            for (int i = 0; i < 4; i++) v += Pr[lane + 32 * i] * w1v[i];
            v = warp_sum(v);
            if (lane == 0) g_udot[r * 4 + x] = v;
        }
        float v = 0.f;
#pragma unroll
        for (int i = 0; i < 4; i++) v += rel_emb[r * D + lane + 32 * i] * w2v[i];
        v = warp_sum(v);
        if (lane == 0) g_reldot[r] = v;
    } else if (gw < RREL + 4) {
        const float* bs[4] = {b_hh, b_ht, b_th, b_tt};
        const float* bx = bs[gw - RREL];
        float v = 0.f;
#pragma unroll
        for (int i = 0; i < 4; i++) {
            int dd = lane + 32 * i;
            v += bx[dd] * g_w1[dd];
        }
        v = warp_sum(v);
        if (lane == 0) g_bdot[gw - RREL] = v;
    }
}

// ---------------- K_edge: 4 edges/thread, front-batched (round-5 proven) ----------------
__global__ void __launch_bounds__(256)
k_edge(const int* __restrict__ ht, const int* __restrict__ r_q,
       const int* __restrict__ r_tensor, const int* __restrict__ r_relative,
       const int* __restrict__ h_or_t, const float* __restrict__ corr,
       int M, int nq) {
    const int g = blockIdx.x * 256 + threadIdx.x;
    const int ngroups = M >> 2;
    if (g < ngroups) {
        const int4* htp = (const int4*)ht;
        int4 ev0 = htp[2 * g];
        int4 ev1 = htp[2 * g + 1];
        int4 rtv = ((const int4*)r_tensor)[g];
        int4 rqv = ((const int4*)r_q)[g];
        int4 rrv = ((const int4*)r_relative)[g];
        int4 hsv = ((const int4*)h_or_t)[g];
        int hh[4]  = {ev0.x, ev0.z, ev1.x, ev1.z};
        int tt[4]  = {ev0.y, ev0.w, ev1.y, ev1.w};
        int rta[4] = {rtv.x, rtv.y, rtv.z, rtv.w};
        int rqa[4] = {rqv.x, rqv.y, rqv.z, rqv.w};
        int rra[4] = {rrv.x, rrv.y, rrv.z, rrv.w};
        int hsa[4] = {hsv.x, hsv.y, hsv.z, hsv.w};
        float cv[4];
#pragma unroll
        for (int j = 0; j < 4; j++) cv[j] = __ldg(&corr[rta[j] * RREL + rqa[j]]);
        int mbase = g << 2;
#pragma unroll
        for (int j = 0; j < 4; j++) {
            float gate = 1.f / (1.f + __expf(-cv[j]));
            int idx = ((rra[j] == 0) ? 2 : 0) + ((hsa[j] == 0) ? 1 : 0);
            float s = gate * g_udot[rta[j] * 4 + idx] + g_bdot[idx];
            if (mbase + j < nq) s = 0.f;   // query edges: count only
            asm volatile("red.global.add.v2.f32 [%0], {%1, %2};"
                         :: "l"(&g_acc[hh[j]]), "f"(s), "f"(1.0f) : "memory");
            asm volatile("red.global.add.v2.f32 [%0], {%1, %2};"
                         :: "l"(&g_acc[tt[j]]), "f"(s), "f"(1.0f) : "memory");
        }
    }
    int rem = M & 3;
    if (blockIdx.x == 0 && threadIdx.x < rem) {
        int m = (ngroups << 2) + threadIdx.x;
        int2 e = ((const int2*)ht)[m];
        int rt = r_tensor[m], rq = r_q[m];
        float c = corr[rt * RREL + rq];
        float gate = 1.f / (1.f + __expf(-c));
        int idx = ((r_relative[m] == 0) ? 2 : 0) + ((h_or_t[m] == 0) ? 1 : 0);
        float s = gate * g_udot[rt * 4 + idx] + g_bdot[idx];
        if (m < nq) s = 0.f;
        asm volatile("red.global.add.v2.f32 [%0], {%1, %2};"
                     :: "l"(&g_acc[e.x]), "f"(s), "f"(1.0f) : "memory");
        asm volatile("red.global.add.v2.f32 [%0], {%1, %2};"
                     :: "l"(&g_acc[e.y]), "f"(s), "f"(1.0f) : "memory");
    }
}

// ---------------- K_query ----------------
__global__ void __launch_bounds__(256)
k_query(const int* __restrict__ ht, const int* __restrict__ r_tensor,
        float* __restrict__ out, int nq) {
    int q = blockIdx.x * 256 + threadIdx.x;
    if (q >= nq) return;
    int2 e = ((const int2*)ht)[q];
    float2 ah = g_acc[e.x];
    float2 at = g_acc[e.y];
    out[q] = ah.x / fmaxf(ah.y, 1.f)
           + at.x / fmaxf(at.y, 1.f)
           + g_reldot[r_tensor[q]] + g_ceff;
}

// ---------------- launch ----------------
extern "C" void kernel_launch(void* const* d_in, const int* in_sizes, int n_in,
                              void* d_out, int out_size) {
    const int* ht         = (const int*)d_in[0];
    const int* r_q        = (const int*)d_in[1];
    const int* r_tensor   = (const int*)d_in[2];
    const int* r_relative = (const int*)d_in[3];
    const int* h_or_t     = (const int*)d_in[4];
    int base = n_in - 14;
    const float* rel_emb = (const float*)d_in[base + 0];
    const float* corr    = (const float*)d_in[base + 1];
    const float* W_hh    = (const float*)d_in[base + 2];
    const float* b_hh    = (const float*)d_in[base + 3];
    const float* W_ht    = (const float*)d_in[base + 4];
    const float* b_ht    = (const float*)d_in[base + 5];
    const float* W_th    = (const float*)d_in[base + 6];
    const float* b_th    = (const float*)d_in[base + 7];
    const float* W_tt    = (const float*)d_in[base + 8];
    const float* b_tt    = (const float*)d_in[base + 9];
    const float* W_fin   = (const float*)d_in[base + 10];
    const float* b_fin   = (const float*)d_in[base + 11];
    const float* W_score = (const float*)d_in[base + 12];
    const float* b_score = (const float*)d_in[base + 13];

    int M  = in_sizes[0] / 2;
    int nq = out_size;

    k_A<<<GA_BLOCKS, 256>>>(rel_emb, W_hh, W_ht, W_th, W_tt,
                            W_fin, b_fin, W_score, b_score);
    k_B<<<(RREL + 4 + 7) / 8, 256>>>(rel_emb, b_hh, b_ht, b_th, b_tt);
    int ngroups = M >> 2;
    k_edge<<<(ngroups + 255) / 256, 256>>>(ht, r_q, r_tensor, r_relative,
                                           h_or_t, corr, M, nq);
    k_query<<<(nq + 255) / 256, 256>>>(ht, r_tensor, (float*)d_out, nq);
}

// round 7
// speedup vs baseline: 1.0111x; 1.0111x over previous
#include <cuda_runtime.h>
#include <math.h>

#define D      128
#define RREL   500
#define NNODES 200000

// ---------------- device scratch ----------------
__device__ float2 g_acc[NNODES];   // .x = sum(selected·w1), .y = message count
__device__ float  g_w1[D];         // (W_fin @ W_score)[0:D]
__device__ float  g_w2[D];         // (W_fin @ W_score)[D:2D]
__device__ float  g_p[4][D];       // p_x = W_x @ w1
__device__ float  g_bdot[4];       // b_x · w1
__device__ float  g_ceff;          // b_fin·W_score + b_score
__device__ float  g_udot[RREL * 4];// rel_emb[r] · p_x
__device__ float  g_reldot[RREL];  // rel_emb[r] · w2

__device__ __forceinline__ float warp_sum(float v) {
#pragma unroll
    for (int o = 16; o > 0; o >>= 1) v += __shfl_down_sync(0xffffffffu, v, o);
    return v;
}

// ---------------- K1: zero g_acc + w_eff + ceff ----------------
#define NZB ((NNODES + 255) / 256)
__global__ void __launch_bounds__(256)
k1(const float* __restrict__ W_fin, const float* __restrict__ b_fin,
   const float* __restrict__ W_score, const float* __restrict__ b_score) {
    int b = blockIdx.x;
    if (b < NZB) {
        int i = b * 256 + threadIdx.x;
        if (i < NNODES) g_acc[i] = make_float2(0.f, 0.f);
        return;
    }
    int w = (b - NZB) * 8 + (threadIdx.x >> 5);
    int lane = threadIdx.x & 31;
    if (w < 256) {
        float v = 0.f;
#pragma unroll
        for (int i = 0; i < 4; i++) {
            int d = lane + 32 * i;
            v += W_fin[w * D + d] * W_score[d];
        }
        v = warp_sum(v);
        if (lane == 0) { if (w < D) g_w1[w] = v; else g_w2[w - D] = v; }
    } else if (w == 256) {
        float v = 0.f;
#pragma unroll
        for (int i = 0; i < 4; i++) {
            int d = lane + 32 * i;
            v += b_fin[d] * W_score[d];
        }
        v = warp_sum(v);
        if (lane == 0) g_ceff = v + b_score[0];
    }
}

// ---------------- K2: p_x + bdot (warp per output row) ----------------
__global__ void __launch_bounds__(256)
k2(const float* __restrict__ W_hh, const float* __restrict__ b_hh,
   const float* __restrict__ W_ht, const float* __restrict__ b_ht,
   const float* __restrict__ W_th, const float* __restrict__ b_th,
   const float* __restrict__ W_tt, const float* __restrict__ b_tt) {
    const float* Ws[4] = {W_hh, W_ht, W_th, W_tt};
    const float* bs[4] = {b_hh, b_ht, b_th, b_tt};
    int w = blockIdx.x * 8 + (threadIdx.x >> 5);
    int lane = threadIdx.x & 31;
    if (w < 512) {
        int x = w >> 7, k = w & (D - 1);
        const float* row = Ws[x] + k * D;
        float v = 0.f;
#pragma unroll
        for (int i = 0; i < 4; i++) {
            int d = lane + 32 * i;
            v += row[d] * g_w1[d];
        }
        v = warp_sum(v);
        if (lane == 0) g_p[x][k] = v;
    } else if (w < 516) {
        int x = w - 512;
        float v = 0.f;
#pragma unroll
        for (int i = 0; i < 4; i++) {
            int d = lane + 32 * i;
            v += bs[x][d] * g_w1[d];
        }
        v = warp_sum(v);
        if (lane == 0) g_bdot[x] = v;
    }
}

// ---------------- K3: udot + reldot (warp per relation) ----------------
__global__ void __launch_bounds__(256)
k3(const float* __restrict__ rel_emb) {
    int r = blockIdx.x * 8 + (threadIdx.x >> 5);
    int lane = threadIdx.x & 31;
    if (r >= RREL) return;
    float e0 = rel_emb[r * D + lane];
    float e1 = rel_emb[r * D + lane + 32];
    float e2 = rel_emb[r * D + lane + 64];
    float e3 = rel_emb[r * D + lane + 96];
#pragma unroll
    for (int x = 0; x < 5; x++) {
        const float* c = (x < 4) ? g_p[x] : g_w2;
        float v = e0 * c[lane] + e1 * c[lane + 32] + e2 * c[lane + 64] + e3 * c[lane + 96];
        v = warp_sum(v);
        if (lane == 0) {
            if (x < 4) g_udot[r * 4 + x] = v;
            else       g_reldot[r] = v;
        }
    }
}

// ---------------- K4: edges, 4 per thread, front-batched ----------------
__global__ void __launch_bounds__(256)
k_edge(const int* __restrict__ ht, const int* __restrict__ r_q,
       const int* __restrict__ r_tensor, const int* __restrict__ r_relative,
       const int* __restrict__ h_or_t, const float* __restrict__ corr,
       int M, int nq) {
    const int g = blockIdx.x * 256 + threadIdx.x;
    const int ngroups = M >> 2;
    if (g < ngroups) {
        const int4* htp = (const int4*)ht;
        int4 ev0 = htp[2 * g];
        int4 ev1 = htp[2 * g + 1];
        int4 rtv = ((const int4*)r_tensor)[g];
        int4 rqv = ((const int4*)r_q)[g];
        int4 rrv = ((const int4*)r_relative)[g];
        int4 hsv = ((const int4*)h_or_t)[g];
        int hh[4]  = {ev0.x, ev0.z, ev1.x, ev1.z};
        int tt[4]  = {ev0.y, ev0.w, ev1.y, ev1.w};
        int rta[4] = {rtv.x, rtv.y, rtv.z, rtv.w};
        int rqa[4] = {rqv.x, rqv.y, rqv.z, rqv.w};
        int rra[4] = {rrv.x, rrv.y, rrv.z, rrv.w};
        int hsa[4] = {hsv.x, hsv.y, hsv.z, hsv.w};
        float cv[4];
#pragma unroll
        for (int j = 0; j < 4; j++) cv[j] = __ldg(&corr[rta[j] * RREL + rqa[j]]);
        int mbase = g << 2;
#pragma unroll
        for (int j = 0; j < 4; j++) {
            float gate = 1.f / (1.f + __expf(-cv[j]));
            int idx = ((rra[j] == 0) ? 2 : 0) + ((hsa[j] == 0) ? 1 : 0);
            float s = gate * g_udot[rta[j] * 4 + idx] + g_bdot[idx];
            if (mbase + j < nq) s = 0.f;   // query edges: count only
            asm volatile("red.global.add.v2.f32 [%0], {%1, %2};"
                         :: "l"(&g_acc[hh[j]]), "f"(s), "f"(1.0f) : "memory");
            asm volatile("red.global.add.v2.f32 [%0], {%1, %2};"
                         :: "l"(&g_acc[tt[j]]), "f"(s), "f"(1.0f) : "memory");
        }
    }
    int rem = M & 3;
    if (blockIdx.x == 0 && threadIdx.x < rem) {
        int m = (ngroups << 2) + threadIdx.x;
        int2 e = ((const int2*)ht)[m];
        int rt = r_tensor[m], rq = r_q[m];
        float c = corr[rt * RREL + rq];
        float gate = 1.f / (1.f + __expf(-c));
        int idx = ((r_relative[m] == 0) ? 2 : 0) + ((h_or_t[m] == 0) ? 1 : 0);
        float s = gate * g_udot[rt * 4 + idx] + g_bdot[idx];
        if (m < nq) s = 0.f;
        asm volatile("red.global.add.v2.f32 [%0], {%1, %2};"
                     :: "l"(&g_acc[e.x]), "f"(s), "f"(1.0f) : "memory");
        asm volatile("red.global.add.v2.f32 [%0], {%1, %2};"
                     :: "l"(&g_acc[e.y]), "f"(s), "f"(1.0f) : "memory");
    }
}

// ---------------- K5: queries, 4 per thread, front-batched gathers ----------------
__device__ __forceinline__ float2 ldcg_f2(const float2* p) {
    float2 r;
    asm volatile("ld.global.cg.v2.f32 {%0, %1}, [%2];"
                 : "=f"(r.x), "=f"(r.y) : "l"(p));
    return r;
}

__global__ void __launch_bounds__(256)
k_query(const int* __restrict__ ht, const int* __restrict__ r_tensor,
        float* __restrict__ out, int nq) {
    const int g = blockIdx.x * 256 + threadIdx.x;   // group of 4 queries
    const int ngroups = nq >> 2;
    if (g < ngroups) {
        const int4* htp = (const int4*)ht;
        int4 ev0 = htp[2 * g];
        int4 ev1 = htp[2 * g + 1];
        int4 rtv = ((const int4*)r_tensor)[g];
        int hh[4] = {ev0.x, ev0.z, ev1.x, ev1.z};
        int tt[4] = {ev0.y, ev0.w, ev1.y, ev1.w};
        int rta[4] = {rtv.x, rtv.y, rtv.z, rtv.w};
        // 12 independent gathers in flight
        float2 ah[4], at[4];
        float rd[4];
#pragma unroll
        for (int j = 0; j < 4; j++) ah[j] = ldcg_f2(&g_acc[hh[j]]);
#pragma unroll
        for (int j = 0; j < 4; j++) at[j] = ldcg_f2(&g_acc[tt[j]]);
#pragma unroll
        for (int j = 0; j < 4; j++) rd[j] = g_reldot[rta[j]];
        float4 o;
        float* op = (float*)&o;
#pragma unroll
        for (int j = 0; j < 4; j++)
            op[j] = ah[j].x / fmaxf(ah[j].y, 1.f)
                  + at[j].x / fmaxf(at[j].y, 1.f)
                  + rd[j] + g_ceff;
        ((float4*)out)[g] = o;
    }
    int rem = nq & 3;
    if (blockIdx.x == 0 && threadIdx.x < rem) {
        int q = (ngroups << 2) + threadIdx.x;
        int2 e = ((const int2*)ht)[q];
        float2 ah = ldcg_f2(&g_acc[e.x]);
        float2 at = ldcg_f2(&g_acc[e.y]);
        out[q] = ah.x / fmaxf(ah.y, 1.f) + at.x / fmaxf(at.y, 1.f)
               + g_reldot[r_tensor[q]] + g_ceff;
    }
}

// ---------------- launch ----------------
extern "C" void kernel_launch(void* const* d_in, const int* in_sizes, int n_in,
                              void* d_out, int out_size) {
    const int* ht         = (const int*)d_in[0];
    const int* r_q        = (const int*)d_in[1];
    const int* r_tensor   = (const int*)d_in[2];
    const int* r_relative = (const int*)d_in[3];
    const int* h_or_t     = (const int*)d_in[4];
    int base = n_in - 14;
    const float* rel_emb = (const float*)d_in[base + 0];
    const float* corr    = (const float*)d_in[base + 1];
    const float* W_hh    = (const float*)d_in[base + 2];
    const float* b_hh    = (const float*)d_in[base + 3];
    const float* W_ht    = (const float*)d_in[base + 4];
    const float* b_ht    = (const float*)d_in[base + 5];
    const float* W_th    = (const float*)d_in[base + 6];
    const float* b_th    = (const float*)d_in[base + 7];
    const float* W_tt    = (const float*)d_in[base + 8];
    const float* b_tt    = (const float*)d_in[base + 9];
    const float* W_fin   = (const float*)d_in[base + 10];
    const float* b_fin   = (const float*)d_in[base + 11];
    const float* W_score = (const float*)d_in[base + 12];
    const float* b_score = (const float*)d_in[base + 13];

    int M  = in_sizes[0] / 2;
    int nq = out_size;

    k1<<<NZB + 33, 256>>>(W_fin, b_fin, W_score, b_score);
    k2<<<65, 256>>>(W_hh, b_hh, W_ht, b_ht, W_th, b_th, W_tt, b_tt);
    k3<<<(RREL + 7) / 8, 256>>>(rel_emb);
    int eg = (M >> 2);
    k_edge<<<(eg + 255) / 256, 256>>>(ht, r_q, r_tensor, r_relative, h_or_t,
                                      corr, M, nq);
    int qg = (nq >> 2);
    k_query<<<(qg + 255) / 256 + (qg == 0), 256>>>(ht, r_tensor, (float*)d_out, nq);
}

// round 8
// speedup vs baseline: 1.0949x; 1.0828x over previous
#include <cuda_runtime.h>
#include <math.h>

#define D      128
#define RREL   500
#define NNODES 200000
#define PGB    148          // persistent pre-kernel grid
#define PTPB   256
#define PNT    (PGB * PTPB)

// ---------------- device scratch ----------------
__device__ float2 g_acc[NNODES];    // .x = sum(selected·w1), .y = message count
__device__ float  g_w1[D];
__device__ float  g_w2[D];
__device__ float  g_p[4][D];
__device__ float  g_bdot[4];
__device__ float  g_ceff;
__device__ float  g_udot[RREL * 4];
__device__ float  g_reldot[RREL];
__device__ unsigned g_bar;          // monotonic ticket counter (graph-replay safe)

__device__ __forceinline__ float warp_sum(float v) {
#pragma unroll
    for (int o = 16; o > 0; o >>= 1) v += __shfl_down_sync(0xffffffffu, v, o);
    return v;
}

__device__ __forceinline__ void grid_barrier() {
    __syncthreads();
    if (threadIdx.x == 0) {
        __threadfence();
        unsigned old = atomicAdd(&g_bar, 1u);
        unsigned target = old - (old % PGB) + PGB;
        unsigned v;
        do {
            asm volatile("ld.acquire.gpu.u32 %0, [%1];" : "=r"(v) : "l"(&g_bar));
        } while (v < target);
    }
    __syncthreads();
}

// ---------------- K1: all precompute + zeroing (persistent, 2 barriers) ----------------
__global__ void __launch_bounds__(PTPB)
k_pre(const float* __restrict__ rel_emb,
      const float* __restrict__ W_hh, const float* __restrict__ b_hh,
      const float* __restrict__ W_ht, const float* __restrict__ b_ht,
      const float* __restrict__ W_th, const float* __restrict__ b_th,
      const float* __restrict__ W_tt, const float* __restrict__ b_tt,
      const float* __restrict__ W_fin, const float* __restrict__ b_fin,
      const float* __restrict__ W_score, const float* __restrict__ b_score) {
    const int tid  = threadIdx.x;
    const int gt   = blockIdx.x * PTPB + tid;
    const int lane = tid & 31;
    const int gw   = gt >> 5;      // 0..1183

    // stage 0: w_eff & ceff (warps 0..256), zero g_acc (everyone)
    if (gw < 256) {
        float v = 0.f;
#pragma unroll
        for (int i = 0; i < 4; i++) {
            int d = lane + 32 * i;
            v += W_fin[gw * D + d] * W_score[d];
        }
        v = warp_sum(v);
        if (lane == 0) { if (gw < D) g_w1[gw] = v; else g_w2[gw - D] = v; }
    } else if (gw == 256) {
        float v = 0.f;
#pragma unroll
        for (int i = 0; i < 4; i++) {
            int d = lane + 32 * i;
            v += b_fin[d] * W_score[d];
        }
        v = warp_sum(v);
        if (lane == 0) g_ceff = v + b_score[0];
    }
    for (int i = gt; i < NNODES; i += PNT) g_acc[i] = make_float2(0.f, 0.f);
    grid_barrier();

    // stage 1: p_x = W_x @ w1, bdot
    {
        const float* Ws[4] = {W_hh, W_ht, W_th, W_tt};
        const float* bs[4] = {b_hh, b_ht, b_th, b_tt};
        if (gw < 512) {
            int x = gw >> 7, k = gw & (D - 1);
            const float* row = Ws[x] + k * D;
            float v = 0.f;
#pragma unroll
            for (int i = 0; i < 4; i++) {
                int d = lane + 32 * i;
                v += row[d] * g_w1[d];
            }
            v = warp_sum(v);
            if (lane == 0) g_p[x][k] = v;
        } else if (gw < 516) {
            int x = gw - 512;
            float v = 0.f;
#pragma unroll
            for (int i = 0; i < 4; i++) {
                int d = lane + 32 * i;
                v += bs[x][d] * g_w1[d];
            }
            v = warp_sum(v);
            if (lane == 0) g_bdot[x] = v;
        }
    }
    grid_barrier();

    // stage 2: udot / reldot (warp per relation)
    if (gw < RREL) {
        int r = gw;
        float e0 = rel_emb[r * D + lane];
        float e1 = rel_emb[r * D + lane + 32];
        float e2 = rel_emb[r * D + lane + 64];
        float e3 = rel_emb[r * D + lane + 96];
#pragma unroll
        for (int x = 0; x < 5; x++) {
            const float* c = (x < 4) ? g_p[x] : g_w2;
            float v = e0 * c[lane] + e1 * c[lane + 32] + e2 * c[lane + 64] + e3 * c[lane + 96];
            v = warp_sum(v);
            if (lane == 0) {
                if (x < 4) g_udot[r * 4 + x] = v;
                else       g_reldot[r] = v;
            }
        }
    }
}

// ---------------- K2: edges, 2 per thread, front-batched ----------------
__global__ void __launch_bounds__(256)
k_edge(const int* __restrict__ ht, const int* __restrict__ r_q,
       const int* __restrict__ r_tensor, const int* __restrict__ r_relative,
       const int* __restrict__ h_or_t, const float* __restrict__ corr,
       int M, int nq) {
    const int g = blockIdx.x * 256 + threadIdx.x;   // pair of edges
    const int ngroups = M >> 1;
    if (g < ngroups) {
        // 5 independent coalesced loads (1×16B + 4×8B)
        int4 ev  = ((const int4*)ht)[g];             // h0,t0,h1,t1
        int2 rtv = ((const int2*)r_tensor)[g];
        int2 rqv = ((const int2*)r_q)[g];
        int2 rrv = ((const int2*)r_relative)[g];
        int2 hsv = ((const int2*)h_or_t)[g];
        int hh[2]  = {ev.x, ev.z};
        int tt[2]  = {ev.y, ev.w};
        int rta[2] = {rtv.x, rtv.y};
        int rqa[2] = {rqv.x, rqv.y};
        int rra[2] = {rrv.x, rrv.y};
        int hsa[2] = {hsv.x, hsv.y};
        // 2 independent gathers in flight
        float cv[2];
#pragma unroll
        for (int j = 0; j < 2; j++) cv[j] = __ldg(&corr[rta[j] * RREL + rqa[j]]);
        int mbase = g << 1;
#pragma unroll
        for (int j = 0; j < 2; j++) {
            float gate = 1.f / (1.f + __expf(-cv[j]));
            int idx = ((rra[j] == 0) ? 2 : 0) + ((hsa[j] == 0) ? 1 : 0);
            float s = gate * g_udot[rta[j] * 4 + idx] + g_bdot[idx];
            if (mbase + j < nq) s = 0.f;   // query edges: count only
            asm volatile("red.global.add.v2.f32 [%0], {%1, %2};"
                         :: "l"(&g_acc[hh[j]]), "f"(s), "f"(1.0f) : "memory");
            asm volatile("red.global.add.v2.f32 [%0], {%1, %2};"
                         :: "l"(&g_acc[tt[j]]), "f"(s), "f"(1.0f) : "memory");
        }
    }
    // tail (M odd)
    if ((M & 1) && blockIdx.x == 0 && threadIdx.x == 0) {
        int m = M - 1;
        int2 e = ((const int2*)ht)[m];
        int rt = r_tensor[m], rq = r_q[m];
        float c = corr[rt * RREL + rq];
        float gate = 1.f / (1.f + __expf(-c));
        int idx = ((r_relative[m] == 0) ? 2 : 0) + ((h_or_t[m] == 0) ? 1 : 0);
        float s = gate * g_udot[rt * 4 + idx] + g_bdot[idx];
        if (m < nq) s = 0.f;
        asm volatile("red.global.add.v2.f32 [%0], {%1, %2};"
                     :: "l"(&g_acc[e.x]), "f"(s), "f"(1.0f) : "memory");
        asm volatile("red.global.add.v2.f32 [%0], {%1, %2};"
                     :: "l"(&g_acc[e.y]), "f"(s), "f"(1.0f) : "memory");
    }
}

// ---------------- K3: queries, 4 per thread, front-batched gathers ----------------
__device__ __forceinline__ float2 ldcg_f2(const float2* p) {
    float2 r;
    asm volatile("ld.global.cg.v2.f32 {%0, %1}, [%2];"
                 : "=f"(r.x), "=f"(r.y) : "l"(p));
    return r;
}

__global__ void __launch_bounds__(256)
k_query(const int* __restrict__ ht, const int* __restrict__ r_tensor,
        float* __restrict__ out, int nq) {
    const int g = blockIdx.x * 256 + threadIdx.x;   // group of 4 queries
    const int ngroups = nq >> 2;
    if (g < ngroups) {
        const int4* htp = (const int4*)ht;
        int4 ev0 = htp[2 * g];
        int4 ev1 = htp[2 * g + 1];
        int4 rtv = ((const int4*)r_tensor)[g];
        int hh[4] = {ev0.x, ev0.z, ev1.x, ev1.z};
        int tt[4] = {ev0.y, ev0.w, ev1.y, ev1.w};
        int rta[4] = {rtv.x, rtv.y, rtv.z, rtv.w};
        float2 ah[4], at[4];
        float rd[4];
#pragma unroll
        for (int j = 0; j < 4; j++) ah[j] = ldcg_f2(&g_acc[hh[j]]);
#pragma unroll
        for (int j = 0; j < 4; j++) at[j] = ldcg_f2(&g_acc[tt[j]]);
#pragma unroll
        for (int j = 0; j < 4; j++) rd[j] = g_reldot[rta[j]];
        float4 o;
        float* op = (float*)&o;
#pragma unroll
        for (int j = 0; j < 4; j++)
            op[j] = ah[j].x / fmaxf(ah[j].y, 1.f)
                  + at[j].x / fmaxf(at[j].y, 1.f)
                  + rd[j] + g_ceff;
        ((float4*)out)[g] = o;
    }
    int rem = nq & 3;
    if (blockIdx.x == 0 && threadIdx.x < rem) {
        int q = (ngroups << 2) + threadIdx.x;
        int2 e = ((const int2*)ht)[q];
        float2 ah = ldcg_f2(&g_acc[e.x]);
        float2 at = ldcg_f2(&g_acc[e.y]);
        out[q] = ah.x / fmaxf(ah.y, 1.f) + at.x / fmaxf(at.y, 1.f)
               + g_reldot[r_tensor[q]] + g_ceff;
    }
}

// ---------------- launch ----------------
extern "C" void kernel_launch(void* const* d_in, const int* in_sizes, int n_in,
                              void* d_out, int out_size) {
    const int* ht         = (const int*)d_in[0];
    const int* r_q        = (const int*)d_in[1];
    const int* r_tensor   = (const int*)d_in[2];
    const int* r_relative = (const int*)d_in[3];
    const int* h_or_t     = (const int*)d_in[4];
    int base = n_in - 14;
    const float* rel_emb = (const float*)d_in[base + 0];
    const float* corr    = (const float*)d_in[base + 1];
    const float* W_hh    = (const float*)d_in[base + 2];
    const float* b_hh    = (const float*)d_in[base + 3];
    const float* W_ht    = (const float*)d_in[base + 4];
    const float* b_ht    = (const float*)d_in[base + 5];
    const float* W_th    = (const float*)d_in[base + 6];
    const float* b_th    = (const float*)d_in[base + 7];
    const float* W_tt    = (const float*)d_in[base + 8];
    const float* b_tt    = (const float*)d_in[base + 9];
    const float* W_fin   = (const float*)d_in[base + 10];
    const float* b_fin   = (const float*)d_in[base + 11];
    const float* W_score = (const float*)d_in[base + 12];
    const float* b_score = (const float*)d_in[base + 13];

    int M  = in_sizes[0] / 2;
    int nq = out_size;

    k_pre<<<PGB, PTPB>>>(rel_emb, W_hh, b_hh, W_ht, b_ht, W_th, b_th,
                         W_tt, b_tt, W_fin, b_fin, W_score, b_score);
    int eg = M >> 1;
    k_edge<<<(eg + 255) / 256, 256>>>(ht, r_q, r_tensor, r_relative, h_or_t,
                                      corr, M, nq);
    int qg = nq >> 2;
    k_query<<<(qg + 255) / 256 + (qg == 0), 256>>>(ht, r_tensor, (float*)d_out, nq);
}

// round 9
// speedup vs baseline: 1.1116x; 1.0153x over previous
#include <cuda_runtime.h>
#include <math.h>

#define D      128
#define RREL   500
#define NNODES 200000
#define PGB    148
#define PTPB   256
#define PNT    (PGB * PTPB)

// ---------------- device scratch ----------------
__device__ float2 g_acc[NNODES];
__device__ float  g_w1[D];
__device__ float  g_w2[D];
__device__ float  g_p[4][D];
__device__ float  g_bdot[4];
__device__ float  g_ceff;
__device__ float  g_udot[RREL * 4];
__device__ float  g_reldot[RREL];
__device__ unsigned g_bar;          // monotonic ticket counter (graph-replay safe)

__device__ __forceinline__ float warp_sum(float v) {
#pragma unroll
    for (int o = 16; o > 0; o >>= 1) v += __shfl_down_sync(0xffffffffu, v, o);
    return v;
}

// Monotonic grid barrier with nanosleep backoff (no L2 poll storm).
__device__ __forceinline__ void grid_barrier() {
    __syncthreads();
    if (threadIdx.x == 0) {
        __threadfence();
        unsigned old = atomicAdd(&g_bar, 1u);
        unsigned target = old - (old % PGB) + PGB;
        unsigned v;
        do {
            asm volatile("ld.acquire.gpu.u32 %0, [%1];" : "=r"(v) : "l"(&g_bar));
            if (v >= target) break;
            __nanosleep(64);
        } while (true);
    }
    __syncthreads();
}

// ---------------- K1: precompute + zeroing (persistent, 2 barriers) ----------------
__global__ void __launch_bounds__(PTPB)
k_pre(const float* __restrict__ rel_emb,
      const float* __restrict__ W_hh, const float* __restrict__ b_hh,
      const float* __restrict__ W_ht, const float* __restrict__ b_ht,
      const float* __restrict__ W_th, const float* __restrict__ b_th,
      const float* __restrict__ W_tt, const float* __restrict__ b_tt,
      const float* __restrict__ W_fin, const float* __restrict__ b_fin,
      const float* __restrict__ W_score, const float* __restrict__ b_score) {
    const int tid  = threadIdx.x;
    const int gt   = blockIdx.x * PTPB + tid;
    const int lane = tid & 31;
    const int gw   = gt >> 5;

    // stage 0: w_eff & ceff (warps 0..256), zero g_acc (everyone)
    if (gw < 256) {
        float v = 0.f;
#pragma unroll
        for (int i = 0; i < 4; i++) {
            int d = lane + 32 * i;
            v += W_fin[gw * D + d] * W_score[d];
        }
        v = warp_sum(v);
        if (lane == 0) { if (gw < D) g_w1[gw] = v; else g_w2[gw - D] = v; }
    } else if (gw == 256) {
        float v = 0.f;
#pragma unroll
        for (int i = 0; i < 4; i++) {
            int d = lane + 32 * i;
            v += b_fin[d] * W_score[d];
        }
        v = warp_sum(v);
        if (lane == 0) g_ceff = v + b_score[0];
    }
    for (int i = gt; i < NNODES; i += PNT) g_acc[i] = make_float2(0.f, 0.f);
    grid_barrier();

    // stage 1: p_x = W_x @ w1, bdot
    {
        const float* Ws[4] = {W_hh, W_ht, W_th, W_tt};
        const float* bs[4] = {b_hh, b_ht, b_th, b_tt};
        if (gw < 512) {
            int x = gw >> 7, k = gw & (D - 1);
            const float* row = Ws[x] + k * D;
            float v = 0.f;
#pragma unroll
            for (int i = 0; i < 4; i++) {
                int d = lane + 32 * i;
                v += row[d] * g_w1[d];
            }
            v = warp_sum(v);
            if (lane == 0) g_p[x][k] = v;
        } else if (gw < 516) {
            int x = gw - 512;
            float v = 0.f;
#pragma unroll
            for (int i = 0; i < 4; i++) {
                int d = lane + 32 * i;
                v += bs[x][d] * g_w1[d];
            }
            v = warp_sum(v);
            if (lane == 0) g_bdot[x] = v;
        }
    }
    grid_barrier();

    // stage 2: udot / reldot (warp per relation)
    if (gw < RREL) {
        int r = gw;
        float e0 = rel_emb[r * D + lane];
        float e1 = rel_emb[r * D + lane + 32];
        float e2 = rel_emb[r * D + lane + 64];
        float e3 = rel_emb[r * D + lane + 96];
#pragma unroll
        for (int x = 0; x < 5; x++) {
            const float* c = (x < 4) ? g_p[x] : g_w2;
            float v = e0 * c[lane] + e1 * c[lane + 32] + e2 * c[lane + 64] + e3 * c[lane + 96];
            v = warp_sum(v);
            if (lane == 0) {
                if (x < 4) g_udot[r * 4 + x] = v;
                else       g_reldot[r] = v;
            }
        }
    }
}

// ---------------- K2: edges, 2 per thread, front-batched ----------------
__global__ void __launch_bounds__(256)
k_edge(const int* __restrict__ ht, const int* __restrict__ r_q,
       const int* __restrict__ r_tensor, const int* __restrict__ r_relative,
       const int* __restrict__ h_or_t, const float* __restrict__ corr,
       int M, int nq) {
    const int g = blockIdx.x * 256 + threadIdx.x;
    const int ngroups = M >> 1;
    if (g < ngroups) {
        int4 ev  = ((const int4*)ht)[g];
        int2 rtv = ((const int2*)r_tensor)[g];
        int2 rqv = ((const int2*)r_q)[g];
        int2 rrv = ((const int2*)r_relative)[g];
        int2 hsv = ((const int2*)h_or_t)[g];
        int hh[2]  = {ev.x, ev.z};
        int tt[2]  = {ev.y, ev.w};
        int rta[2] = {rtv.x, rtv.y};
        int rqa[2] = {rqv.x, rqv.y};
        int rra[2] = {rrv.x, rrv.y};
        int hsa[2] = {hsv.x, hsv.y};
        float cv[2];
#pragma unroll
        for (int j = 0; j < 2; j++) cv[j] = __ldg(&corr[rta[j] * RREL + rqa[j]]);
        int mbase = g << 1;
#pragma unroll
        for (int j = 0; j < 2; j++) {
            float gate = 1.f / (1.f + __expf(-cv[j]));
            int idx = ((rra[j] == 0) ? 2 : 0) + ((hsa[j] == 0) ? 1 : 0);
            float s = gate * g_udot[rta[j] * 4 + idx] + g_bdot[idx];
            if (mbase + j < nq) s = 0.f;
            asm volatile("red.global.add.v2.f32 [%0], {%1, %2};"
                         :: "l"(&g_acc[hh[j]]), "f"(s), "f"(1.0f) : "memory");
            asm volatile("red.global.add.v2.f32 [%0], {%1, %2};"
                         :: "l"(&g_acc[tt[j]]), "f"(s), "f"(1.0f) : "memory");
        }
    }
    if ((M & 1) && blockIdx.x == 0 && threadIdx.x == 0) {
        int m = M - 1;
        int2 e = ((const int2*)ht)[m];
        int rt = r_tensor[m], rq = r_q[m];
        float c = corr[rt * RREL + rq];
        float gate = 1.f / (1.f + __expf(-c));
        int idx = ((r_relative[m] == 0) ? 2 : 0) + ((h_or_t[m] == 0) ? 1 : 0);
        float s = gate * g_udot[rt * 4 + idx] + g_bdot[idx];
        if (m < nq) s = 0.f;
        asm volatile("red.global.add.v2.f32 [%0], {%1, %2};"
                     :: "l"(&g_acc[e.x]), "f"(s), "f"(1.0f) : "memory");
        asm volatile("red.global.add.v2.f32 [%0], {%1, %2};"
                     :: "l"(&g_acc[e.y]), "f"(s), "f"(1.0f) : "memory");
    }
}

// ---------------- K3: queries, 2 per thread, front-batched gathers ----------------
__device__ __forceinline__ float2 ldcg_f2(const float2* p) {
    float2 r;
    asm volatile("ld.global.cg.v2.f32 {%0, %1}, [%2];"
                 : "=f"(r.x), "=f"(r.y) : "l"(p));
    return r;
}

__global__ void __launch_bounds__(256)
k_query(const int* __restrict__ ht, const int* __restrict__ r_tensor,
        float* __restrict__ out, int nq) {
    const int g = blockIdx.x * 256 + threadIdx.x;   // pair of queries
    const int ngroups = nq >> 1;
    if (g < ngroups) {
        int4 ev  = ((const int4*)ht)[g];             // h0,t0,h1,t1
        int2 rtv = ((const int2*)r_tensor)[g];
        int hh[2] = {ev.x, ev.z};
        int tt[2] = {ev.y, ev.w};
        // 6 independent gathers in flight
        float2 ah[2], at[2];
        float rd[2];
#pragma unroll
        for (int j = 0; j < 2; j++) ah[j] = ldcg_f2(&g_acc[hh[j]]);
#pragma unroll
        for (int j = 0; j < 2; j++) at[j] = ldcg_f2(&g_acc[tt[j]]);
        rd[0] = g_reldot[rtv.x];
        rd[1] = g_reldot[rtv.y];
        float2 o;
        o.x = ah[0].x / fmaxf(ah[0].y, 1.f) + at[0].x / fmaxf(at[0].y, 1.f) + rd[0] + g_ceff;
        o.y = ah[1].x / fmaxf(ah[1].y, 1.f) + at[1].x / fmaxf(at[1].y, 1.f) + rd[1] + g_ceff;
        ((float2*)out)[g] = o;
    }
    if ((nq & 1) && blockIdx.x == 0 && threadIdx.x == 0) {
        int q = nq - 1;
        int2 e = ((const int2*)ht)[q];
        float2 ah = ldcg_f2(&g_acc[e.x]);
        float2 at = ldcg_f2(&g_acc[e.y]);
        out[q] = ah.x / fmaxf(ah.y, 1.f) + at.x / fmaxf(at.y, 1.f)
               + g_reldot[r_tensor[q]] + g_ceff;
    }
}

// ---------------- launch ----------------
extern "C" void kernel_launch(void* const* d_in, const int* in_sizes, int n_in,
                              void* d_out, int out_size) {
    const int* ht         = (const int*)d_in[0];
    const int* r_q        = (const int*)d_in[1];
    const int* r_tensor   = (const int*)d_in[2];
    const int* r_relative = (const int*)d_in[3];
    const int* h_or_t     = (const int*)d_in[4];
    int base = n_in - 14;
    const float* rel_emb = (const float*)d_in[base + 0];
    const float* corr    = (const float*)d_in[base + 1];
    const float* W_hh    = (const float*)d_in[base + 2];
    const float* b_hh    = (const float*)d_in[base + 3];
    const float* W_ht    = (const float*)d_in[base + 4];
    const float* b_ht    = (const float*)d_in[base + 5];
    const float* W_th    = (const float*)d_in[base + 6];
    const float* b_th    = (const float*)d_in[base + 7];
    const float* W_tt    = (const float*)d_in[base + 8];
    const float* b_tt    = (const float*)d_in[base + 9];
    const float* W_fin   = (const float*)d_in[base + 10];
    const float* b_fin   = (const float*)d_in[base + 11];
    const float* W_score = (const float*)d_in[base + 12];
    const float* b_score = (const float*)d_in[base + 13];

    int M  = in_sizes[0] / 2;
    int nq = out_size;

    k_pre<<<PGB, PTPB>>>(rel_emb, W_hh, b_hh, W_ht, b_ht, W_th, b_th,
                         W_tt, b_tt, W_fin, b_fin, W_score, b_score);
    int eg = M >> 1;
    k_edge<<<(eg + 255) / 256, 256>>>(ht, r_q, r_tensor, r_relative, h_or_t,
                                      corr, M, nq);
    int qg = nq >> 1;
    k_query<<<(qg + 255) / 256 + (qg == 0), 256>>>(ht, r_tensor, (float*)d_out, nq);
}